// round 12
// baseline (speedup 1.0000x reference)
#include <cuda_runtime.h>
#include <cuda_fp16.h>
#include <cstdint>

// ============================================================
// QuarotFP16Linear: out[t,o] = sum_i (x[t,i]*sx[t]) * ((w[o,i]-off[o,g])*ws[o,g])
// T=8192, I=4096, O=11008, G=32 (group=128)
//
// tcgen05 unavailable (harness PTX target is compute_103, not 103a).
// fp16 mma.sync.m16n8k16 GEMM, fp32 accum, cp.async 3-stage, SW128 + ldmatrix.
// R11 model: tensor (2048 cyc) and smem crossbar (2048 cyc) per k-tile-pair are
// co-saturated at ~57% each -> overlap-bound.
// R12: interleave at finer grain: per ks, [LDSM-B(next), 8 MMA, LDSM-A(next),
// 8 MMA]; move cp.async issue to ks=1 slot (out of post-barrier burst window).
// ============================================================

#define TOKENS 8192
#define IN_F   4096
#define OUT_F  11008
#define GROUPS 32

#define BM 128
#define BN 128
#define BK 64                 // 64 fp16 = 128 bytes per row (SW128 atom)
#define KTILES (IN_F / BK)    // 64
#define STAGES 3

// fp16 operands, dequant pre-applied
__device__ __half g_Xh[(size_t)TOKENS * IN_F];   // 64 MB
__device__ __half g_Wh[(size_t)OUT_F  * IN_F];   // 90 MB

// ------------------------------------------------------------
// helpers
// ------------------------------------------------------------
__device__ __forceinline__ uint32_t smem_u32(const void* p) {
    uint32_t a;
    asm("{ .reg .u64 t; cvta.to.shared.u64 t, %1; cvt.u32.u64 %0, t; }" : "=r"(a) : "l"(p));
    return a;
}

__device__ __forceinline__ void cp_async16(uint32_t smem_dst, const void* gmem_src) {
    asm volatile("cp.async.cg.shared.global [%0], [%1], 16;"
                 :: "r"(smem_dst), "l"(gmem_src));
}
#define CP_ASYNC_COMMIT() asm volatile("cp.async.commit_group;" ::: "memory")
#define CP_ASYNC_WAIT1()  asm volatile("cp.async.wait_group 1;" ::: "memory")

__device__ __forceinline__ void ldsm_x4(uint32_t& r0, uint32_t& r1, uint32_t& r2,
                                        uint32_t& r3, uint32_t addr) {
    asm volatile("ldmatrix.sync.aligned.m8n8.x4.shared.b16 {%0,%1,%2,%3}, [%4];"
                 : "=r"(r0), "=r"(r1), "=r"(r2), "=r"(r3) : "r"(addr));
}

__device__ __forceinline__ void mma_16816(float* c, const uint32_t* a, const uint32_t* b) {
    asm volatile(
        "mma.sync.aligned.m16n8k16.row.col.f32.f16.f16.f32 "
        "{%0,%1,%2,%3}, {%4,%5,%6,%7}, {%8,%9}, {%0,%1,%2,%3};"
        : "+f"(c[0]), "+f"(c[1]), "+f"(c[2]), "+f"(c[3])
        : "r"(a[0]), "r"(a[1]), "r"(a[2]), "r"(a[3]), "r"(b[0]), "r"(b[1]));
}

// ------------------------------------------------------------
// Merged prep kernel: fold dequant into fp16 operand tensors.
// ------------------------------------------------------------
static constexpr size_t XV4 = (size_t)TOKENS * IN_F / 4;   // 8388608
static constexpr size_t WV4 = (size_t)OUT_F  * IN_F / 4;   // 11272192

__global__ void prep_kernel(const float* __restrict__ x,
                            const float* __restrict__ sx,
                            const float* __restrict__ w,
                            const float* __restrict__ ws,
                            const float* __restrict__ wo,
                            __half* __restrict__ xh,
                            __half* __restrict__ wh) {
    size_t idx = (size_t)blockIdx.x * blockDim.x + threadIdx.x;
    if (idx < XV4) {
        size_t base = idx * 4;
        int t = (int)(base >> 12);   // IN_F = 4096
        float s = __ldg(sx + t);
        float4 v = *reinterpret_cast<const float4*>(x + base);
        __half2* p = reinterpret_cast<__half2*>(xh + base);
        p[0] = __floats2half2_rn(v.x * s, v.y * s);
        p[1] = __floats2half2_rn(v.z * s, v.w * s);
    } else {
        size_t base = (idx - XV4) * 4;
        if (base >= (size_t)OUT_F * IN_F) return;
        int o = (int)(base >> 12);
        int g = (int)((base & 4095) >> 7);   // group of 128
        float s = __ldg(ws + (size_t)o * GROUPS + g);
        float f = __ldg(wo + (size_t)o * GROUPS + g);
        float4 v = *reinterpret_cast<const float4*>(w + base);
        __half2* p = reinterpret_cast<__half2*>(wh + base);
        p[0] = __floats2half2_rn((v.x - f) * s, (v.y - f) * s);
        p[1] = __floats2half2_rn((v.z - f) * s, (v.w - f) * s);
    }
}

// ------------------------------------------------------------
// GEMM: out[T,O] = Xh[T,K] · Wh[O,K]^T
// SMEM per stage: A 128x128B + B 128x128B = 32KB, SW128. 3 stages = 96KB,
// 2 CTAs/SM, 16 warps/SM (RF-limited: 512 thr x 128 regs).
// ------------------------------------------------------------
static constexpr int A_TILE_BYTES = BM * 128;          // 16384
static constexpr int B_TILE_BYTES = BN * 128;          // 16384
static constexpr int STAGE_BYTES  = A_TILE_BYTES + B_TILE_BYTES;   // 32768
static constexpr int SMEM_TOTAL   = STAGES * STAGE_BYTES;          // 98304

__device__ __forceinline__ void load_tile(const __half* __restrict__ A,
                                          const __half* __restrict__ B,
                                          int t0, int o0, int tid,
                                          uint32_t smem_base, int kt, int stage) {
    int row   = tid >> 1;            // 0..127
    int cbase = (tid & 1) * 4;       // 16B chunks 0-3 or 4-7
    int k0 = kt * BK;
    const __half* ga = A + (size_t)(t0 + row) * IN_F + k0 + cbase * 8;
    const __half* gb = B + (size_t)(o0 + row) * IN_F + k0 + cbase * 8;
    uint32_t sw = (uint32_t)((row & 7) * 16);
    uint32_t sa = smem_base + stage * STAGE_BYTES + row * 128;
    uint32_t sb = sa + A_TILE_BYTES;
#pragma unroll
    for (int c = 0; c < 4; ++c) {
        uint32_t off = ((uint32_t)((cbase + c) * 16)) ^ sw;
        cp_async16(sa + off, ga + c * 8);
        cp_async16(sb + off, gb + c * 8);
    }
}

// Split fragment loaders: A-half (4 LDSM) and B-half (2 LDSM).
// Bases are row bases (col bits 0-6 clear), so base + (col ^ sw) is exact.
__device__ __forceinline__ void load_frags_A(uint32_t stage_base, int ksp,
                                             uint32_t aa[4][4],
                                             uint32_t a_base, uint32_t a_colsel,
                                             uint32_t sw_mask) {
    uint32_t a_col = ((uint32_t)(ksp * 32) + a_colsel) ^ sw_mask;
    uint32_t abase = stage_base + a_base + a_col;
#pragma unroll
    for (int mt = 0; mt < 4; ++mt)
        ldsm_x4(aa[mt][0], aa[mt][1], aa[mt][2], aa[mt][3], abase + mt * 2048);
}

__device__ __forceinline__ void load_frags_B(uint32_t stage_base, int ksp,
                                             uint32_t bb[4][2],
                                             uint32_t b_base, uint32_t b_colsel,
                                             uint32_t sw_mask) {
    uint32_t b_col = ((uint32_t)(ksp * 32) + b_colsel) ^ sw_mask;
    uint32_t bbase = stage_base + b_base + b_col;
#pragma unroll
    for (int p = 0; p < 2; ++p)
        ldsm_x4(bb[p * 2][0], bb[p * 2][1], bb[p * 2 + 1][0], bb[p * 2 + 1][1],
                bbase + p * 2048);
}

__global__ void __launch_bounds__(256, 2)
gemm_f16_kernel(const __half* __restrict__ A,    // [TOKENS, IN_F]
                const __half* __restrict__ B,    // [OUT_F, IN_F]
                float* __restrict__ out) {       // [TOKENS, OUT_F]
    extern __shared__ char smem[];
    uint32_t smem_base = smem_u32(smem);
    int tid  = threadIdx.x;
    int wid  = tid >> 5;
    int lane = tid & 31;
    int o0 = blockIdx.x * BN;
    int t0 = blockIdx.y * BM;

    int warp_m = wid & 1;    // 2 warps along M (64 rows each)
    int warp_n = wid >> 1;   // 4 warps along N (32 cols each)
    int stag   = (wid >> 2) * 2;   // warps 4-7 traverse k-slices rotated by 2

    float acc[4][4][4];
#pragma unroll
    for (int mt = 0; mt < 4; ++mt)
#pragma unroll
        for (int nt = 0; nt < 4; ++nt)
#pragma unroll
            for (int j = 0; j < 4; ++j) acc[mt][nt][j] = 0.f;

    // Row bases (col bits 0-6 clear), per-lane resolved.
    uint32_t sw_mask  = (uint32_t)((lane & 7) * 16);
    uint32_t a_base   = (uint32_t)((warp_m * 64 + (lane & 15)) * 128);
    uint32_t a_colsel = (uint32_t)((lane >> 4) * 16);
    uint32_t b_base   = (uint32_t)(A_TILE_BYTES +
                        (warp_n * 32 + ((lane >> 4) * 8) + (lane & 7)) * 128);
    uint32_t b_colsel = (uint32_t)(((lane >> 3) & 1) * 16);

    // Double-buffered fragments
    uint32_t aa[2][4][4];
    uint32_t bb[2][4][2];

    // ---- pipeline prologue ----
    load_tile(A, B, t0, o0, tid, smem_base, 0, 0);
    CP_ASYNC_COMMIT();
    load_tile(A, B, t0, o0, tid, smem_base, 1, 1);
    CP_ASYNC_COMMIT();
    CP_ASYNC_WAIT1();            // tile 0 resident (tile 1 may be in flight)
    __syncthreads();
    // Prime fragments for (kt=0, logical ks=0)
    load_frags_B(smem_base, stag, bb[0], b_base, b_colsel, sw_mask);
    load_frags_A(smem_base, stag, aa[0], a_base, a_colsel, sw_mask);

    for (int kt = 0; kt < KTILES; ++kt) {
        uint32_t stage_base = smem_base + (kt % STAGES) * STAGE_BYTES;
#pragma unroll
        for (int ks = 0; ks < 4; ++ks) {
            int cur = ks & 1;
            int nxt = cur ^ 1;

            // cp.async for tile kt+2 issued mid-tile (ks=1), away from the
            // post-barrier LDSM burst. Stage (kt+2)%3's last readers were at
            // iter kt-1 (<= ks2 slot), separated by the barrier at kt-1/ks3.
            if (ks == 1) {
                if (kt + 2 < KTILES)
                    load_tile(A, B, t0, o0, tid, smem_base, kt + 2, (kt + 2) % STAGES);
                CP_ASYNC_COMMIT();   // exactly one commit per iter
            }

            // B fragments for next ks, then first half of MMAs.
            if (ks < 3) {
                int ksp = (ks + 1 + stag) & 3;
                load_frags_B(stage_base, ksp, bb[nxt], b_base, b_colsel, sw_mask);
            }
#pragma unroll
            for (int mt = 0; mt < 2; ++mt)
#pragma unroll
                for (int nt = 0; nt < 4; ++nt)
                    mma_16816(acc[mt][nt], aa[cur][mt], bb[cur][nt]);

            // A fragments for next ks (or cross-tile preload), second half.
            if (ks < 3) {
                int ksp = (ks + 1 + stag) & 3;
                load_frags_A(stage_base, ksp, aa[nxt], a_base, a_colsel, sw_mask);
            } else if (kt + 1 < KTILES) {
                CP_ASYNC_WAIT1();     // tile kt+1 complete (this warp's groups)
                __syncthreads();      // publish all warps' cp.async writes
                uint32_t nsb = smem_base + ((kt + 1) % STAGES) * STAGE_BYTES;
                load_frags_B(nsb, stag, bb[0], b_base, b_colsel, sw_mask);
                load_frags_A(nsb, stag, aa[0], a_base, a_colsel, sw_mask);
            }
#pragma unroll
            for (int mt = 2; mt < 4; ++mt)
#pragma unroll
                for (int nt = 0; nt < 4; ++nt)
                    mma_16816(acc[mt][nt], aa[cur][mt], bb[cur][nt]);
        }
    }

    // ---- epilogue: direct global stores ----
    int r_base = t0 + warp_m * 64 + (lane >> 2);
    int c_base = o0 + warp_n * 32 + (lane & 3) * 2;
#pragma unroll
    for (int mt = 0; mt < 4; ++mt) {
#pragma unroll
        for (int nt = 0; nt < 4; ++nt) {
            float* p0 = out + (size_t)(r_base + mt * 16) * OUT_F + c_base + nt * 8;
            float* p1 = p0 + (size_t)8 * OUT_F;
            *reinterpret_cast<float2*>(p0) = make_float2(acc[mt][nt][0], acc[mt][nt][1]);
            *reinterpret_cast<float2*>(p1) = make_float2(acc[mt][nt][2], acc[mt][nt][3]);
        }
    }
}

// ------------------------------------------------------------
// Launch
// ------------------------------------------------------------
extern "C" void kernel_launch(void* const* d_in, const int* in_sizes, int n_in,
                              void* d_out, int out_size) {
    const float* x  = (const float*)d_in[0];   // [8192, 4096]
    const float* sx = (const float*)d_in[1];   // [8192, 1]
    const float* w  = (const float*)d_in[2];   // [11008, 4096]
    const float* ws = (const float*)d_in[3];   // [11008, 32]
    const float* wo = (const float*)d_in[4];   // [11008, 32]
    float* out = (float*)d_out;

    void* xh_p = nullptr;
    void* wh_p = nullptr;
    cudaGetSymbolAddress(&xh_p, g_Xh);
    cudaGetSymbolAddress(&wh_p, g_Wh);

    cudaFuncSetAttribute(gemm_f16_kernel,
                         cudaFuncAttributeMaxDynamicSharedMemorySize, SMEM_TOTAL);

    size_t total_v4 = XV4 + WV4;
    prep_kernel<<<(unsigned)((total_v4 + 255) / 256), 256>>>(
        x, sx, w, ws, wo, (__half*)xh_p, (__half*)wh_p);

    dim3 grid(OUT_F / BN, TOKENS / BM);   // (86, 64) — x along N keeps W panels L2-resident
    gemm_f16_kernel<<<grid, 256, SMEM_TOTAL>>>((const __half*)xh_p, (const __half*)wh_p, out);
}

// round 13
// speedup vs baseline: 1.5865x; 1.5865x over previous
#include <cuda_runtime.h>
#include <cuda_fp16.h>
#include <cstdint>

// ============================================================
// QuarotFP16Linear: out[t,o] = sum_i (x[t,i]*sx[t]) * ((w[o,i]-off[o,g])*ws[o,g])
// T=8192, I=4096, O=11008, G=32 (group=128)
//
// tcgen05 unavailable (harness PTX target is compute_103, not 103a).
// fp16 mma.sync.m16n8k16 GEMM, fp32 accum, cp.async 3-stage, SW128 + ldmatrix.
// R12 post-mortem: fine-grained A/B-split interleave caused register spills
// (regs 127, L1 62% local traffic) -> +47%. Reverted.
// R13 = R11 + (a) cp.async issue moved to ks=1 slot (no extra live state),
//            (b) kt loop unrolled x3 so stage offsets are static.
// ============================================================

#define TOKENS 8192
#define IN_F   4096
#define OUT_F  11008
#define GROUPS 32

#define BM 128
#define BN 128
#define BK 64                 // 64 fp16 = 128 bytes per row (SW128 atom)
#define KTILES (IN_F / BK)    // 64
#define STAGES 3

// fp16 operands, dequant pre-applied
__device__ __half g_Xh[(size_t)TOKENS * IN_F];   // 64 MB
__device__ __half g_Wh[(size_t)OUT_F  * IN_F];   // 90 MB

// ------------------------------------------------------------
// helpers
// ------------------------------------------------------------
__device__ __forceinline__ uint32_t smem_u32(const void* p) {
    uint32_t a;
    asm("{ .reg .u64 t; cvta.to.shared.u64 t, %1; cvt.u32.u64 %0, t; }" : "=r"(a) : "l"(p));
    return a;
}

__device__ __forceinline__ void cp_async16(uint32_t smem_dst, const void* gmem_src) {
    asm volatile("cp.async.cg.shared.global [%0], [%1], 16;"
                 :: "r"(smem_dst), "l"(gmem_src));
}
#define CP_ASYNC_COMMIT() asm volatile("cp.async.commit_group;" ::: "memory")
#define CP_ASYNC_WAIT1()  asm volatile("cp.async.wait_group 1;" ::: "memory")

__device__ __forceinline__ void ldsm_x4(uint32_t& r0, uint32_t& r1, uint32_t& r2,
                                        uint32_t& r3, uint32_t addr) {
    asm volatile("ldmatrix.sync.aligned.m8n8.x4.shared.b16 {%0,%1,%2,%3}, [%4];"
                 : "=r"(r0), "=r"(r1), "=r"(r2), "=r"(r3) : "r"(addr));
}

__device__ __forceinline__ void mma_16816(float* c, const uint32_t* a, const uint32_t* b) {
    asm volatile(
        "mma.sync.aligned.m16n8k16.row.col.f32.f16.f16.f32 "
        "{%0,%1,%2,%3}, {%4,%5,%6,%7}, {%8,%9}, {%0,%1,%2,%3};"
        : "+f"(c[0]), "+f"(c[1]), "+f"(c[2]), "+f"(c[3])
        : "r"(a[0]), "r"(a[1]), "r"(a[2]), "r"(a[3]), "r"(b[0]), "r"(b[1]));
}

// ------------------------------------------------------------
// Merged prep kernel: fold dequant into fp16 operand tensors.
// ------------------------------------------------------------
static constexpr size_t XV4 = (size_t)TOKENS * IN_F / 4;   // 8388608
static constexpr size_t WV4 = (size_t)OUT_F  * IN_F / 4;   // 11272192

__global__ void prep_kernel(const float* __restrict__ x,
                            const float* __restrict__ sx,
                            const float* __restrict__ w,
                            const float* __restrict__ ws,
                            const float* __restrict__ wo,
                            __half* __restrict__ xh,
                            __half* __restrict__ wh) {
    size_t idx = (size_t)blockIdx.x * blockDim.x + threadIdx.x;
    if (idx < XV4) {
        size_t base = idx * 4;
        int t = (int)(base >> 12);   // IN_F = 4096
        float s = __ldg(sx + t);
        float4 v = *reinterpret_cast<const float4*>(x + base);
        __half2* p = reinterpret_cast<__half2*>(xh + base);
        p[0] = __floats2half2_rn(v.x * s, v.y * s);
        p[1] = __floats2half2_rn(v.z * s, v.w * s);
    } else {
        size_t base = (idx - XV4) * 4;
        if (base >= (size_t)OUT_F * IN_F) return;
        int o = (int)(base >> 12);
        int g = (int)((base & 4095) >> 7);   // group of 128
        float s = __ldg(ws + (size_t)o * GROUPS + g);
        float f = __ldg(wo + (size_t)o * GROUPS + g);
        float4 v = *reinterpret_cast<const float4*>(w + base);
        __half2* p = reinterpret_cast<__half2*>(wh + base);
        p[0] = __floats2half2_rn((v.x - f) * s, (v.y - f) * s);
        p[1] = __floats2half2_rn((v.z - f) * s, (v.w - f) * s);
    }
}

// ------------------------------------------------------------
// GEMM: out[T,O] = Xh[T,K] · Wh[O,K]^T
// SMEM per stage: A 128x128B + B 128x128B = 32KB, SW128. 3 stages = 96KB,
// 2 CTAs/SM, 16 warps/SM (RF-limited: 512 thr x 128 regs).
// ------------------------------------------------------------
static constexpr int A_TILE_BYTES = BM * 128;          // 16384
static constexpr int B_TILE_BYTES = BN * 128;          // 16384
static constexpr int STAGE_BYTES  = A_TILE_BYTES + B_TILE_BYTES;   // 32768
static constexpr int SMEM_TOTAL   = STAGES * STAGE_BYTES;          // 98304

__device__ __forceinline__ void load_tile(const __half* __restrict__ A,
                                          const __half* __restrict__ B,
                                          int t0, int o0, int tid,
                                          uint32_t smem_base, int kt, int stage) {
    int row   = tid >> 1;            // 0..127
    int cbase = (tid & 1) * 4;       // 16B chunks 0-3 or 4-7
    int k0 = kt * BK;
    const __half* ga = A + (size_t)(t0 + row) * IN_F + k0 + cbase * 8;
    const __half* gb = B + (size_t)(o0 + row) * IN_F + k0 + cbase * 8;
    uint32_t sw = (uint32_t)((row & 7) * 16);
    uint32_t sa = smem_base + stage * STAGE_BYTES + row * 128;
    uint32_t sb = sa + A_TILE_BYTES;
#pragma unroll
    for (int c = 0; c < 4; ++c) {
        uint32_t off = ((uint32_t)((cbase + c) * 16)) ^ sw;
        cp_async16(sa + off, ga + c * 8);
        cp_async16(sb + off, gb + c * 8);
    }
}

// Load one ks-step's fragments (A: 4 LDSM.x4, B: 2 LDSM.x4, one block so
// ptxas can batch them). Bases are row bases (col bits 0-6 clear).
__device__ __forceinline__ void load_frags(uint32_t stage_base, int ksp,
                                           uint32_t aa[4][4], uint32_t bb[4][2],
                                           uint32_t a_base, uint32_t b_base,
                                           uint32_t a_colsel, uint32_t b_colsel,
                                           uint32_t sw_mask) {
    uint32_t a_col = ((uint32_t)(ksp * 32) + a_colsel) ^ sw_mask;
    uint32_t b_col = ((uint32_t)(ksp * 32) + b_colsel) ^ sw_mask;
    uint32_t abase = stage_base + a_base + a_col;
    uint32_t bbase = stage_base + b_base + b_col;
#pragma unroll
    for (int mt = 0; mt < 4; ++mt)
        ldsm_x4(aa[mt][0], aa[mt][1], aa[mt][2], aa[mt][3], abase + mt * 2048);
#pragma unroll
    for (int p = 0; p < 2; ++p)
        ldsm_x4(bb[p * 2][0], bb[p * 2][1], bb[p * 2 + 1][0], bb[p * 2 + 1][1],
                bbase + p * 2048);
}

__global__ void __launch_bounds__(256, 2)
gemm_f16_kernel(const __half* __restrict__ A,    // [TOKENS, IN_F]
                const __half* __restrict__ B,    // [OUT_F, IN_F]
                float* __restrict__ out) {       // [TOKENS, OUT_F]
    extern __shared__ char smem[];
    uint32_t smem_base = smem_u32(smem);
    int tid  = threadIdx.x;
    int wid  = tid >> 5;
    int lane = tid & 31;
    int o0 = blockIdx.x * BN;
    int t0 = blockIdx.y * BM;

    int warp_m = wid & 1;    // 2 warps along M (64 rows each)
    int warp_n = wid >> 1;   // 4 warps along N (32 cols each)
    int stag   = (wid >> 2) * 2;   // warps 4-7 traverse k-slices rotated by 2

    float acc[4][4][4];
#pragma unroll
    for (int mt = 0; mt < 4; ++mt)
#pragma unroll
        for (int nt = 0; nt < 4; ++nt)
#pragma unroll
            for (int j = 0; j < 4; ++j) acc[mt][nt][j] = 0.f;

    // Row bases (col bits 0-6 clear), per-lane resolved.
    uint32_t sw_mask  = (uint32_t)((lane & 7) * 16);
    uint32_t a_base   = (uint32_t)((warp_m * 64 + (lane & 15)) * 128);
    uint32_t a_colsel = (uint32_t)((lane >> 4) * 16);
    uint32_t b_base   = (uint32_t)(A_TILE_BYTES +
                        (warp_n * 32 + ((lane >> 4) * 8) + (lane & 7)) * 128);
    uint32_t b_colsel = (uint32_t)(((lane >> 3) & 1) * 16);

    // Double-buffered fragments
    uint32_t aa[2][4][4];
    uint32_t bb[2][4][2];

    // ---- pipeline prologue ----
    load_tile(A, B, t0, o0, tid, smem_base, 0, 0);
    CP_ASYNC_COMMIT();
    load_tile(A, B, t0, o0, tid, smem_base, 1, 1);
    CP_ASYNC_COMMIT();
    CP_ASYNC_WAIT1();            // tile 0 resident (tile 1 may be in flight)
    __syncthreads();
    // Prime fragments for (kt=0, logical ks=0)
    load_frags(smem_base, stag, aa[0], bb[0],
               a_base, b_base, a_colsel, b_colsel, sw_mask);

#pragma unroll 3
    for (int kt = 0; kt < KTILES; ++kt) {
        uint32_t stage_base = smem_base + (kt % STAGES) * STAGE_BYTES;
#pragma unroll
        for (int ks = 0; ks < 4; ++ks) {
            // cp.async for tile kt+2 issued at ks=1, away from the post-barrier
            // LDSM burst. Stage (kt+2)%3's last readers were at iter kt-1
            // (<= ks2), separated by the barrier at kt-1/ks3.
            if (ks == 1) {
                if (kt + 2 < KTILES)
                    load_tile(A, B, t0, o0, tid, smem_base, kt + 2, (kt + 2) % STAGES);
                CP_ASYNC_COMMIT();   // exactly one commit per iter
            }
            if (ks < 3) {
                int ksp = (ks + 1 + stag) & 3;
                load_frags(stage_base, ksp, aa[(ks + 1) & 1], bb[(ks + 1) & 1],
                           a_base, b_base, a_colsel, b_colsel, sw_mask);
            } else if (kt + 1 < KTILES) {
                // Cross-tile preload, shadowed by the ks=3 MMA block below.
                CP_ASYNC_WAIT1();     // tile kt+1 complete (this warp's groups)
                __syncthreads();      // publish all warps' cp.async writes
                load_frags(smem_base + ((kt + 1) % STAGES) * STAGE_BYTES, stag,
                           aa[0], bb[0],
                           a_base, b_base, a_colsel, b_colsel, sw_mask);
            }
            int cur = ks & 1;
#pragma unroll
            for (int mt = 0; mt < 4; ++mt)
#pragma unroll
                for (int nt = 0; nt < 4; ++nt)
                    mma_16816(acc[mt][nt], aa[cur][mt], bb[cur][nt]);
        }
    }

    // ---- epilogue: direct global stores ----
    int r_base = t0 + warp_m * 64 + (lane >> 2);
    int c_base = o0 + warp_n * 32 + (lane & 3) * 2;
#pragma unroll
    for (int mt = 0; mt < 4; ++mt) {
#pragma unroll
        for (int nt = 0; nt < 4; ++nt) {
            float* p0 = out + (size_t)(r_base + mt * 16) * OUT_F + c_base + nt * 8;
            float* p1 = p0 + (size_t)8 * OUT_F;
            *reinterpret_cast<float2*>(p0) = make_float2(acc[mt][nt][0], acc[mt][nt][1]);
            *reinterpret_cast<float2*>(p1) = make_float2(acc[mt][nt][2], acc[mt][nt][3]);
        }
    }
}

// ------------------------------------------------------------
// Launch
// ------------------------------------------------------------
extern "C" void kernel_launch(void* const* d_in, const int* in_sizes, int n_in,
                              void* d_out, int out_size) {
    const float* x  = (const float*)d_in[0];   // [8192, 4096]
    const float* sx = (const float*)d_in[1];   // [8192, 1]
    const float* w  = (const float*)d_in[2];   // [11008, 4096]
    const float* ws = (const float*)d_in[3];   // [11008, 32]
    const float* wo = (const float*)d_in[4];   // [11008, 32]
    float* out = (float*)d_out;

    void* xh_p = nullptr;
    void* wh_p = nullptr;
    cudaGetSymbolAddress(&xh_p, g_Xh);
    cudaGetSymbolAddress(&wh_p, g_Wh);

    cudaFuncSetAttribute(gemm_f16_kernel,
                         cudaFuncAttributeMaxDynamicSharedMemorySize, SMEM_TOTAL);

    size_t total_v4 = XV4 + WV4;
    prep_kernel<<<(unsigned)((total_v4 + 255) / 256), 256>>>(
        x, sx, w, ws, wo, (__half*)xh_p, (__half*)wh_p);

    dim3 grid(OUT_F / BN, TOKENS / BM);   // (86, 64) — x along N keeps W panels L2-resident
    gemm_f16_kernel<<<grid, 256, SMEM_TOTAL>>>((const __half*)xh_p, (const __half*)wh_p, out);
}

// round 14
// speedup vs baseline: 1.5867x; 1.0001x over previous
#include <cuda_runtime.h>
#include <cuda_fp16.h>
#include <cstdint>

// ============================================================
// QuarotFP16Linear: out[t,o] = sum_i (x[t,i]*sx[t]) * ((w[o,i]-off[o,g])*ws[o,g])
// T=8192, I=4096, O=11008, G=32 (group=128)
//
// tcgen05 unavailable (harness PTX target is compute_103, not 103a).
// fp16 mma.sync.m16n8k16 GEMM, fp32 accum, cp.async 3-stage, SW128 + ldmatrix.
// R13 (2058us, tensor 61%): cross-tile pipeline + ks=1 cp.async + unroll-3.
// R14: CTA anti-phase stagger. Co-resident CTAs (consecutive waves of 148)
// are phase-locked -> their per-tile barrier convoys coincide and drain the
// tensor pipe. Odd-wave CTAs spin ~1700 cyc at start so the partner CTA's
// MMA phase covers this CTA's barrier window.
// ============================================================

#define TOKENS 8192
#define IN_F   4096
#define OUT_F  11008
#define GROUPS 32

#define BM 128
#define BN 128
#define BK 64                 // 64 fp16 = 128 bytes per row (SW128 atom)
#define KTILES (IN_F / BK)    // 64
#define STAGES 3

// fp16 operands, dequant pre-applied
__device__ __half g_Xh[(size_t)TOKENS * IN_F];   // 64 MB
__device__ __half g_Wh[(size_t)OUT_F  * IN_F];   // 90 MB

// ------------------------------------------------------------
// helpers
// ------------------------------------------------------------
__device__ __forceinline__ uint32_t smem_u32(const void* p) {
    uint32_t a;
    asm("{ .reg .u64 t; cvta.to.shared.u64 t, %1; cvt.u32.u64 %0, t; }" : "=r"(a) : "l"(p));
    return a;
}

__device__ __forceinline__ void cp_async16(uint32_t smem_dst, const void* gmem_src) {
    asm volatile("cp.async.cg.shared.global [%0], [%1], 16;"
                 :: "r"(smem_dst), "l"(gmem_src));
}
#define CP_ASYNC_COMMIT() asm volatile("cp.async.commit_group;" ::: "memory")
#define CP_ASYNC_WAIT1()  asm volatile("cp.async.wait_group 1;" ::: "memory")

__device__ __forceinline__ void ldsm_x4(uint32_t& r0, uint32_t& r1, uint32_t& r2,
                                        uint32_t& r3, uint32_t addr) {
    asm volatile("ldmatrix.sync.aligned.m8n8.x4.shared.b16 {%0,%1,%2,%3}, [%4];"
                 : "=r"(r0), "=r"(r1), "=r"(r2), "=r"(r3) : "r"(addr));
}

__device__ __forceinline__ void mma_16816(float* c, const uint32_t* a, const uint32_t* b) {
    asm volatile(
        "mma.sync.aligned.m16n8k16.row.col.f32.f16.f16.f32 "
        "{%0,%1,%2,%3}, {%4,%5,%6,%7}, {%8,%9}, {%0,%1,%2,%3};"
        : "+f"(c[0]), "+f"(c[1]), "+f"(c[2]), "+f"(c[3])
        : "r"(a[0]), "r"(a[1]), "r"(a[2]), "r"(a[3]), "r"(b[0]), "r"(b[1]));
}

// ------------------------------------------------------------
// Merged prep kernel: fold dequant into fp16 operand tensors.
// ------------------------------------------------------------
static constexpr size_t XV4 = (size_t)TOKENS * IN_F / 4;   // 8388608
static constexpr size_t WV4 = (size_t)OUT_F  * IN_F / 4;   // 11272192

__global__ void prep_kernel(const float* __restrict__ x,
                            const float* __restrict__ sx,
                            const float* __restrict__ w,
                            const float* __restrict__ ws,
                            const float* __restrict__ wo,
                            __half* __restrict__ xh,
                            __half* __restrict__ wh) {
    size_t idx = (size_t)blockIdx.x * blockDim.x + threadIdx.x;
    if (idx < XV4) {
        size_t base = idx * 4;
        int t = (int)(base >> 12);   // IN_F = 4096
        float s = __ldg(sx + t);
        float4 v = *reinterpret_cast<const float4*>(x + base);
        __half2* p = reinterpret_cast<__half2*>(xh + base);
        p[0] = __floats2half2_rn(v.x * s, v.y * s);
        p[1] = __floats2half2_rn(v.z * s, v.w * s);
    } else {
        size_t base = (idx - XV4) * 4;
        if (base >= (size_t)OUT_F * IN_F) return;
        int o = (int)(base >> 12);
        int g = (int)((base & 4095) >> 7);   // group of 128
        float s = __ldg(ws + (size_t)o * GROUPS + g);
        float f = __ldg(wo + (size_t)o * GROUPS + g);
        float4 v = *reinterpret_cast<const float4*>(w + base);
        __half2* p = reinterpret_cast<__half2*>(wh + base);
        p[0] = __floats2half2_rn((v.x - f) * s, (v.y - f) * s);
        p[1] = __floats2half2_rn((v.z - f) * s, (v.w - f) * s);
    }
}

// ------------------------------------------------------------
// GEMM: out[T,O] = Xh[T,K] · Wh[O,K]^T
// SMEM per stage: A 128x128B + B 128x128B = 32KB, SW128. 3 stages = 96KB,
// 2 CTAs/SM, 16 warps/SM (RF-limited: 512 thr x 128 regs).
// ------------------------------------------------------------
static constexpr int A_TILE_BYTES = BM * 128;          // 16384
static constexpr int B_TILE_BYTES = BN * 128;          // 16384
static constexpr int STAGE_BYTES  = A_TILE_BYTES + B_TILE_BYTES;   // 32768
static constexpr int SMEM_TOTAL   = STAGES * STAGE_BYTES;          // 98304

__device__ __forceinline__ void load_tile(const __half* __restrict__ A,
                                          const __half* __restrict__ B,
                                          int t0, int o0, int tid,
                                          uint32_t smem_base, int kt, int stage) {
    int row   = tid >> 1;            // 0..127
    int cbase = (tid & 1) * 4;       // 16B chunks 0-3 or 4-7
    int k0 = kt * BK;
    const __half* ga = A + (size_t)(t0 + row) * IN_F + k0 + cbase * 8;
    const __half* gb = B + (size_t)(o0 + row) * IN_F + k0 + cbase * 8;
    uint32_t sw = (uint32_t)((row & 7) * 16);
    uint32_t sa = smem_base + stage * STAGE_BYTES + row * 128;
    uint32_t sb = sa + A_TILE_BYTES;
#pragma unroll
    for (int c = 0; c < 4; ++c) {
        uint32_t off = ((uint32_t)((cbase + c) * 16)) ^ sw;
        cp_async16(sa + off, ga + c * 8);
        cp_async16(sb + off, gb + c * 8);
    }
}

// Load one ks-step's fragments (A: 4 LDSM.x4, B: 2 LDSM.x4, one block so
// ptxas can batch them). Bases are row bases (col bits 0-6 clear).
__device__ __forceinline__ void load_frags(uint32_t stage_base, int ksp,
                                           uint32_t aa[4][4], uint32_t bb[4][2],
                                           uint32_t a_base, uint32_t b_base,
                                           uint32_t a_colsel, uint32_t b_colsel,
                                           uint32_t sw_mask) {
    uint32_t a_col = ((uint32_t)(ksp * 32) + a_colsel) ^ sw_mask;
    uint32_t b_col = ((uint32_t)(ksp * 32) + b_colsel) ^ sw_mask;
    uint32_t abase = stage_base + a_base + a_col;
    uint32_t bbase = stage_base + b_base + b_col;
#pragma unroll
    for (int mt = 0; mt < 4; ++mt)
        ldsm_x4(aa[mt][0], aa[mt][1], aa[mt][2], aa[mt][3], abase + mt * 2048);
#pragma unroll
    for (int p = 0; p < 2; ++p)
        ldsm_x4(bb[p * 2][0], bb[p * 2][1], bb[p * 2 + 1][0], bb[p * 2 + 1][1],
                bbase + p * 2048);
}

__global__ void __launch_bounds__(256, 2)
gemm_f16_kernel(const __half* __restrict__ A,    // [TOKENS, IN_F]
                const __half* __restrict__ B,    // [OUT_F, IN_F]
                float* __restrict__ out) {       // [TOKENS, OUT_F]
    extern __shared__ char smem[];
    uint32_t smem_base = smem_u32(smem);
    int tid  = threadIdx.x;
    int wid  = tid >> 5;
    int lane = tid & 31;
    int o0 = blockIdx.x * BN;
    int t0 = blockIdx.y * BM;

    // ---- CTA anti-phase stagger ----
    // Co-resident CTAs on an SM come from consecutive 148-CTA waves. Delay
    // odd waves ~half a k-tile period so the two CTAs' barrier convoys
    // interleave instead of coinciding (partner's MMA phase covers this
    // CTA's barrier window). Pure delay; output unaffected.
    {
        int linear = blockIdx.x + (int)gridDim.x * blockIdx.y;
        int wave = linear / 148;
        if (wave & 1) {
            uint32_t junk = (uint32_t)tid;
            for (int i = 0; i < 280; ++i)
                asm volatile("add.u32 %0, %0, 1;" : "+r"(junk));
            // keep junk alive without affecting results
            if (junk == 0xFFFFFFFFu) smem[0] = 0;
        }
    }

    int warp_m = wid & 1;    // 2 warps along M (64 rows each)
    int warp_n = wid >> 1;   // 4 warps along N (32 cols each)
    int stag   = (wid >> 2) * 2;   // warps 4-7 traverse k-slices rotated by 2

    float acc[4][4][4];
#pragma unroll
    for (int mt = 0; mt < 4; ++mt)
#pragma unroll
        for (int nt = 0; nt < 4; ++nt)
#pragma unroll
            for (int j = 0; j < 4; ++j) acc[mt][nt][j] = 0.f;

    // Row bases (col bits 0-6 clear), per-lane resolved.
    uint32_t sw_mask  = (uint32_t)((lane & 7) * 16);
    uint32_t a_base   = (uint32_t)((warp_m * 64 + (lane & 15)) * 128);
    uint32_t a_colsel = (uint32_t)((lane >> 4) * 16);
    uint32_t b_base   = (uint32_t)(A_TILE_BYTES +
                        (warp_n * 32 + ((lane >> 4) * 8) + (lane & 7)) * 128);
    uint32_t b_colsel = (uint32_t)(((lane >> 3) & 1) * 16);

    // Double-buffered fragments
    uint32_t aa[2][4][4];
    uint32_t bb[2][4][2];

    // ---- pipeline prologue ----
    load_tile(A, B, t0, o0, tid, smem_base, 0, 0);
    CP_ASYNC_COMMIT();
    load_tile(A, B, t0, o0, tid, smem_base, 1, 1);
    CP_ASYNC_COMMIT();
    CP_ASYNC_WAIT1();            // tile 0 resident (tile 1 may be in flight)
    __syncthreads();
    // Prime fragments for (kt=0, logical ks=0)
    load_frags(smem_base, stag, aa[0], bb[0],
               a_base, b_base, a_colsel, b_colsel, sw_mask);

#pragma unroll 3
    for (int kt = 0; kt < KTILES; ++kt) {
        uint32_t stage_base = smem_base + (kt % STAGES) * STAGE_BYTES;
#pragma unroll
        for (int ks = 0; ks < 4; ++ks) {
            // cp.async for tile kt+2 issued at ks=1, away from the post-barrier
            // LDSM burst. Stage (kt+2)%3's last readers were at iter kt-1
            // (<= ks2), separated by the barrier at kt-1/ks3.
            if (ks == 1) {
                if (kt + 2 < KTILES)
                    load_tile(A, B, t0, o0, tid, smem_base, kt + 2, (kt + 2) % STAGES);
                CP_ASYNC_COMMIT();   // exactly one commit per iter
            }
            if (ks < 3) {
                int ksp = (ks + 1 + stag) & 3;
                load_frags(stage_base, ksp, aa[(ks + 1) & 1], bb[(ks + 1) & 1],
                           a_base, b_base, a_colsel, b_colsel, sw_mask);
            } else if (kt + 1 < KTILES) {
                // Cross-tile preload, shadowed by the ks=3 MMA block below.
                CP_ASYNC_WAIT1();     // tile kt+1 complete (this warp's groups)
                __syncthreads();      // publish all warps' cp.async writes
                load_frags(smem_base + ((kt + 1) % STAGES) * STAGE_BYTES, stag,
                           aa[0], bb[0],
                           a_base, b_base, a_colsel, b_colsel, sw_mask);
            }
            int cur = ks & 1;
#pragma unroll
            for (int mt = 0; mt < 4; ++mt)
#pragma unroll
                for (int nt = 0; nt < 4; ++nt)
                    mma_16816(acc[mt][nt], aa[cur][mt], bb[cur][nt]);
        }
    }

    // ---- epilogue: direct global stores ----
    int r_base = t0 + warp_m * 64 + (lane >> 2);
    int c_base = o0 + warp_n * 32 + (lane & 3) * 2;
#pragma unroll
    for (int mt = 0; mt < 4; ++mt) {
#pragma unroll
        for (int nt = 0; nt < 4; ++nt) {
            float* p0 = out + (size_t)(r_base + mt * 16) * OUT_F + c_base + nt * 8;
            float* p1 = p0 + (size_t)8 * OUT_F;
            *reinterpret_cast<float2*>(p0) = make_float2(acc[mt][nt][0], acc[mt][nt][1]);
            *reinterpret_cast<float2*>(p1) = make_float2(acc[mt][nt][2], acc[mt][nt][3]);
        }
    }
}

// ------------------------------------------------------------
// Launch
// ------------------------------------------------------------
extern "C" void kernel_launch(void* const* d_in, const int* in_sizes, int n_in,
                              void* d_out, int out_size) {
    const float* x  = (const float*)d_in[0];   // [8192, 4096]
    const float* sx = (const float*)d_in[1];   // [8192, 1]
    const float* w  = (const float*)d_in[2];   // [11008, 4096]
    const float* ws = (const float*)d_in[3];   // [11008, 32]
    const float* wo = (const float*)d_in[4];   // [11008, 32]
    float* out = (float*)d_out;

    void* xh_p = nullptr;
    void* wh_p = nullptr;
    cudaGetSymbolAddress(&xh_p, g_Xh);
    cudaGetSymbolAddress(&wh_p, g_Wh);

    cudaFuncSetAttribute(gemm_f16_kernel,
                         cudaFuncAttributeMaxDynamicSharedMemorySize, SMEM_TOTAL);

    size_t total_v4 = XV4 + WV4;
    prep_kernel<<<(unsigned)((total_v4 + 255) / 256), 256>>>(
        x, sx, w, ws, wo, (__half*)xh_p, (__half*)wh_p);

    dim3 grid(OUT_F / BN, TOKENS / BM);   // (86, 64) — x along N keeps W panels L2-resident
    gemm_f16_kernel<<<grid, 256, SMEM_TOTAL>>>((const __half*)xh_p, (const __half*)wh_p, out);
}

// round 17
// speedup vs baseline: 1.7856x; 1.1253x over previous
#include <cuda_runtime.h>
#include <cuda_fp16.h>
#include <cstdint>

// ============================================================
// QuarotFP16Linear: out[t,o] = sum_i (x[t,i]*sx[t]) * ((w[o,i]-off[o,g])*ws[o,g])
// T=8192, I=4096, O=11008, G=32 (group=128)
//
// tcgen05 unavailable (harness PTX target is compute_103, not 103a).
// fp16 mma.sync.m16n8k16 GEMM, fp32 accum, cp.async 3-stage, SW128 + ldmatrix.
// R15/R16 (decoupled mbarrier pipeline) failed twice (deadlock, then IMA under
// warp skew) -> abandoned; back to the proven R13 skeleton (2058us).
// R17 = R13 + (a) 4-phase warp k-slice stagger (was 2-phase),
//            (b) cp.async split: A-half at ks=1, B-half+commit at ks=2
//                (halves instantaneous STS pressure vs LDSM on the crossbar).
// ============================================================

#define TOKENS 8192
#define IN_F   4096
#define OUT_F  11008
#define GROUPS 32

#define BM 128
#define BN 128
#define BK 64                 // 64 fp16 = 128 bytes per row (SW128 atom)
#define KTILES (IN_F / BK)    // 64
#define STAGES 3

// fp16 operands, dequant pre-applied
__device__ __half g_Xh[(size_t)TOKENS * IN_F];   // 64 MB
__device__ __half g_Wh[(size_t)OUT_F  * IN_F];   // 90 MB

// ------------------------------------------------------------
// helpers
// ------------------------------------------------------------
__device__ __forceinline__ uint32_t smem_u32(const void* p) {
    uint32_t a;
    asm("{ .reg .u64 t; cvta.to.shared.u64 t, %1; cvt.u32.u64 %0, t; }" : "=r"(a) : "l"(p));
    return a;
}

__device__ __forceinline__ void cp_async16(uint32_t smem_dst, const void* gmem_src) {
    asm volatile("cp.async.cg.shared.global [%0], [%1], 16;"
                 :: "r"(smem_dst), "l"(gmem_src));
}
#define CP_ASYNC_COMMIT() asm volatile("cp.async.commit_group;" ::: "memory")
#define CP_ASYNC_WAIT1()  asm volatile("cp.async.wait_group 1;" ::: "memory")

__device__ __forceinline__ void ldsm_x4(uint32_t& r0, uint32_t& r1, uint32_t& r2,
                                        uint32_t& r3, uint32_t addr) {
    asm volatile("ldmatrix.sync.aligned.m8n8.x4.shared.b16 {%0,%1,%2,%3}, [%4];"
                 : "=r"(r0), "=r"(r1), "=r"(r2), "=r"(r3) : "r"(addr));
}

__device__ __forceinline__ void mma_16816(float* c, const uint32_t* a, const uint32_t* b) {
    asm volatile(
        "mma.sync.aligned.m16n8k16.row.col.f32.f16.f16.f32 "
        "{%0,%1,%2,%3}, {%4,%5,%6,%7}, {%8,%9}, {%0,%1,%2,%3};"
        : "+f"(c[0]), "+f"(c[1]), "+f"(c[2]), "+f"(c[3])
        : "r"(a[0]), "r"(a[1]), "r"(a[2]), "r"(a[3]), "r"(b[0]), "r"(b[1]));
}

// ------------------------------------------------------------
// Merged prep kernel: fold dequant into fp16 operand tensors.
// ------------------------------------------------------------
static constexpr size_t XV4 = (size_t)TOKENS * IN_F / 4;   // 8388608
static constexpr size_t WV4 = (size_t)OUT_F  * IN_F / 4;   // 11272192

__global__ void prep_kernel(const float* __restrict__ x,
                            const float* __restrict__ sx,
                            const float* __restrict__ w,
                            const float* __restrict__ ws,
                            const float* __restrict__ wo,
                            __half* __restrict__ xh,
                            __half* __restrict__ wh) {
    size_t idx = (size_t)blockIdx.x * blockDim.x + threadIdx.x;
    if (idx < XV4) {
        size_t base = idx * 4;
        int t = (int)(base >> 12);   // IN_F = 4096
        float s = __ldg(sx + t);
        float4 v = *reinterpret_cast<const float4*>(x + base);
        __half2* p = reinterpret_cast<__half2*>(xh + base);
        p[0] = __floats2half2_rn(v.x * s, v.y * s);
        p[1] = __floats2half2_rn(v.z * s, v.w * s);
    } else {
        size_t base = (idx - XV4) * 4;
        if (base >= (size_t)OUT_F * IN_F) return;
        int o = (int)(base >> 12);
        int g = (int)((base & 4095) >> 7);   // group of 128
        float s = __ldg(ws + (size_t)o * GROUPS + g);
        float f = __ldg(wo + (size_t)o * GROUPS + g);
        float4 v = *reinterpret_cast<const float4*>(w + base);
        __half2* p = reinterpret_cast<__half2*>(wh + base);
        p[0] = __floats2half2_rn((v.x - f) * s, (v.y - f) * s);
        p[1] = __floats2half2_rn((v.z - f) * s, (v.w - f) * s);
    }
}

// ------------------------------------------------------------
// GEMM: out[T,O] = Xh[T,K] · Wh[O,K]^T
// SMEM per stage: A 128x128B + B 128x128B = 32KB, SW128. 3 stages = 96KB,
// 2 CTAs/SM, 16 warps/SM (RF-limited: 512 thr x 128 regs).
// ------------------------------------------------------------
static constexpr int A_TILE_BYTES = BM * 128;          // 16384
static constexpr int B_TILE_BYTES = BN * 128;          // 16384
static constexpr int STAGE_BYTES  = A_TILE_BYTES + B_TILE_BYTES;   // 32768
static constexpr int SMEM_TOTAL   = STAGES * STAGE_BYTES;          // 98304

// A-half of a k-tile load: 4x16B per thread.
__device__ __forceinline__ void load_tile_A(const __half* __restrict__ A,
                                            int t0, int tid,
                                            uint32_t smem_base, int kt, int stage) {
    int row   = tid >> 1;
    int cbase = (tid & 1) * 4;
    const __half* ga = A + (size_t)(t0 + row) * IN_F + kt * BK + cbase * 8;
    uint32_t sw = (uint32_t)((row & 7) * 16);
    uint32_t sa = smem_base + stage * STAGE_BYTES + row * 128;
#pragma unroll
    for (int c = 0; c < 4; ++c) {
        uint32_t off = ((uint32_t)((cbase + c) * 16)) ^ sw;
        cp_async16(sa + off, ga + c * 8);
    }
}

// B-half of a k-tile load: 4x16B per thread.
__device__ __forceinline__ void load_tile_B(const __half* __restrict__ B,
                                            int o0, int tid,
                                            uint32_t smem_base, int kt, int stage) {
    int row   = tid >> 1;
    int cbase = (tid & 1) * 4;
    const __half* gb = B + (size_t)(o0 + row) * IN_F + kt * BK + cbase * 8;
    uint32_t sw = (uint32_t)((row & 7) * 16);
    uint32_t sb = smem_base + stage * STAGE_BYTES + A_TILE_BYTES + row * 128;
#pragma unroll
    for (int c = 0; c < 4; ++c) {
        uint32_t off = ((uint32_t)((cbase + c) * 16)) ^ sw;
        cp_async16(sb + off, gb + c * 8);
    }
}

// Load one ks-step's fragments (A: 4 LDSM.x4, B: 2 LDSM.x4, one block so
// ptxas can batch them). Bases are row bases (col bits 0-6 clear).
__device__ __forceinline__ void load_frags(uint32_t stage_base, int ksp,
                                           uint32_t aa[4][4], uint32_t bb[4][2],
                                           uint32_t a_base, uint32_t b_base,
                                           uint32_t a_colsel, uint32_t b_colsel,
                                           uint32_t sw_mask) {
    uint32_t a_col = ((uint32_t)(ksp * 32) + a_colsel) ^ sw_mask;
    uint32_t b_col = ((uint32_t)(ksp * 32) + b_colsel) ^ sw_mask;
    uint32_t abase = stage_base + a_base + a_col;
    uint32_t bbase = stage_base + b_base + b_col;
#pragma unroll
    for (int mt = 0; mt < 4; ++mt)
        ldsm_x4(aa[mt][0], aa[mt][1], aa[mt][2], aa[mt][3], abase + mt * 2048);
#pragma unroll
    for (int p = 0; p < 2; ++p)
        ldsm_x4(bb[p * 2][0], bb[p * 2][1], bb[p * 2 + 1][0], bb[p * 2 + 1][1],
                bbase + p * 2048);
}

__global__ void __launch_bounds__(256, 2)
gemm_f16_kernel(const __half* __restrict__ A,    // [TOKENS, IN_F]
                const __half* __restrict__ B,    // [OUT_F, IN_F]
                float* __restrict__ out) {       // [TOKENS, OUT_F]
    extern __shared__ char smem[];
    uint32_t smem_base = smem_u32(smem);
    int tid  = threadIdx.x;
    int wid  = tid >> 5;
    int lane = tid & 31;
    int o0 = blockIdx.x * BN;
    int t0 = blockIdx.y * BM;

    int warp_m = wid & 1;    // 2 warps along M (64 rows each)
    int warp_n = wid >> 1;   // 4 warps along N (32 cols each)
    // 4-phase k-slice stagger: SMSP-sharing warps (wid, wid+4) keep delta 2;
    // neighbors also differ. Every warp still covers all 4 slices.
    int stag   = (wid >> 2) * 2 + (wid & 1);

    float acc[4][4][4];
#pragma unroll
    for (int mt = 0; mt < 4; ++mt)
#pragma unroll
        for (int nt = 0; nt < 4; ++nt)
#pragma unroll
            for (int j = 0; j < 4; ++j) acc[mt][nt][j] = 0.f;

    // Row bases (col bits 0-6 clear), per-lane resolved.
    uint32_t sw_mask  = (uint32_t)((lane & 7) * 16);
    uint32_t a_base   = (uint32_t)((warp_m * 64 + (lane & 15)) * 128);
    uint32_t a_colsel = (uint32_t)((lane >> 4) * 16);
    uint32_t b_base   = (uint32_t)(A_TILE_BYTES +
                        (warp_n * 32 + ((lane >> 4) * 8) + (lane & 7)) * 128);
    uint32_t b_colsel = (uint32_t)(((lane >> 3) & 1) * 16);

    // Double-buffered fragments
    uint32_t aa[2][4][4];
    uint32_t bb[2][4][2];

    // ---- pipeline prologue ----
    load_tile_A(A, t0, tid, smem_base, 0, 0);
    load_tile_B(B, o0, tid, smem_base, 0, 0);
    CP_ASYNC_COMMIT();
    load_tile_A(A, t0, tid, smem_base, 1, 1);
    load_tile_B(B, o0, tid, smem_base, 1, 1);
    CP_ASYNC_COMMIT();
    CP_ASYNC_WAIT1();            // tile 0 resident (tile 1 may be in flight)
    __syncthreads();
    // Prime fragments for (kt=0, logical ks=0)
    load_frags(smem_base, stag, aa[0], bb[0],
               a_base, b_base, a_colsel, b_colsel, sw_mask);

#pragma unroll 3
    for (int kt = 0; kt < KTILES; ++kt) {
        uint32_t stage_base = smem_base + (kt % STAGES) * STAGE_BYTES;
#pragma unroll
        for (int ks = 0; ks < 4; ++ks) {
            // cp.async for tile kt+2 split across ks=1 (A) and ks=2 (B+commit),
            // keeping STS bursts small and out of the post-barrier window.
            // Stage (kt+2)%3's last readers were at iter kt-1 (<= ks2),
            // separated by the barrier at kt-1/ks3.
            if (ks == 1 && kt + 2 < KTILES)
                load_tile_A(A, t0, tid, smem_base, kt + 2, (kt + 2) % STAGES);
            if (ks == 2) {
                if (kt + 2 < KTILES)
                    load_tile_B(B, o0, tid, smem_base, kt + 2, (kt + 2) % STAGES);
                CP_ASYNC_COMMIT();   // exactly one commit per iter
            }
            if (ks < 3) {
                int ksp = (ks + 1 + stag) & 3;
                load_frags(stage_base, ksp, aa[(ks + 1) & 1], bb[(ks + 1) & 1],
                           a_base, b_base, a_colsel, b_colsel, sw_mask);
            } else if (kt + 1 < KTILES) {
                // Cross-tile preload, shadowed by the ks=3 MMA block below.
                CP_ASYNC_WAIT1();     // tile kt+1 complete
                __syncthreads();      // publish all warps' cp.async writes
                load_frags(smem_base + ((kt + 1) % STAGES) * STAGE_BYTES, stag,
                           aa[0], bb[0],
                           a_base, b_base, a_colsel, b_colsel, sw_mask);
            }
            int cur = ks & 1;
#pragma unroll
            for (int mt = 0; mt < 4; ++mt)
#pragma unroll
                for (int nt = 0; nt < 4; ++nt)
                    mma_16816(acc[mt][nt], aa[cur][mt], bb[cur][nt]);
        }
    }

    // ---- epilogue: direct global stores ----
    int r_base = t0 + warp_m * 64 + (lane >> 2);
    int c_base = o0 + warp_n * 32 + (lane & 3) * 2;
#pragma unroll
    for (int mt = 0; mt < 4; ++mt) {
#pragma unroll
        for (int nt = 0; nt < 4; ++nt) {
            float* p0 = out + (size_t)(r_base + mt * 16) * OUT_F + c_base + nt * 8;
            float* p1 = p0 + (size_t)8 * OUT_F;
            *reinterpret_cast<float2*>(p0) = make_float2(acc[mt][nt][0], acc[mt][nt][1]);
            *reinterpret_cast<float2*>(p1) = make_float2(acc[mt][nt][2], acc[mt][nt][3]);
        }
    }
}

// ------------------------------------------------------------
// Launch
// ------------------------------------------------------------
extern "C" void kernel_launch(void* const* d_in, const int* in_sizes, int n_in,
                              void* d_out, int out_size) {
    const float* x  = (const float*)d_in[0];   // [8192, 4096]
    const float* sx = (const float*)d_in[1];   // [8192, 1]
    const float* w  = (const float*)d_in[2];   // [11008, 4096]
    const float* ws = (const float*)d_in[3];   // [11008, 32]
    const float* wo = (const float*)d_in[4];   // [11008, 32]
    float* out = (float*)d_out;

    void* xh_p = nullptr;
    void* wh_p = nullptr;
    cudaGetSymbolAddress(&xh_p, g_Xh);
    cudaGetSymbolAddress(&wh_p, g_Wh);

    cudaFuncSetAttribute(gemm_f16_kernel,
                         cudaFuncAttributeMaxDynamicSharedMemorySize, SMEM_TOTAL);

    size_t total_v4 = XV4 + WV4;
    prep_kernel<<<(unsigned)((total_v4 + 255) / 256), 256>>>(
        x, sx, w, ws, wo, (__half*)xh_p, (__half*)wh_p);

    dim3 grid(OUT_F / BN, TOKENS / BM);   // (86, 64) — x along N keeps W panels L2-resident
    gemm_f16_kernel<<<grid, 256, SMEM_TOTAL>>>((const __half*)xh_p, (const __half*)wh_p, out);
}